// round 10
// baseline (speedup 1.0000x reference)
#include <cuda_runtime.h>
#include <cstdint>

#define B_    32
#define NP    32
#define DPD   12
#define LL    1024
#define LOUT  32
#define BIGF  1e30f
#define TPB   320            // 10 warps: 0-1 DP (2 problems each), 2-9 gen (2 per problem)
#define CH    32             // columns per phase
#define NPH   33             // ceil(1056/32)
#define SLOTS 128
#define SLOTM 34             // ring word stride per slot (MUST be even: bank spread -2g)
#define RINGW (SLOTS*SLOTM + 1)  // 4353 words (== 1 mod 32: parity split between pair)
#define XW    1024           // smem: x2 row only
#define SMEMW (XW + 4*RINGW) // 18436 words = 73744 B -> 2 CTAs/SM

__device__ __forceinline__ unsigned long long pk2(float lo, float hi) {
    unsigned long long r;
    asm("mov.b64 %0, {%1,%2};" : "=l"(r) : "f"(lo), "f"(hi));
    return r;
}
__device__ __forceinline__ unsigned long long fma2(unsigned long long a,
                                                   unsigned long long b,
                                                   unsigned long long c) {
    unsigned long long d;
    asm("fma.rn.f32x2 %0, %1, %2, %3;" : "=l"(d) : "l"(a), "l"(b), "l"(c));
    return d;
}
__device__ __forceinline__ unsigned long long add2(unsigned long long a,
                                                   unsigned long long b) {
    unsigned long long d;
    asm("add.rn.f32x2 %0, %1, %2;" : "=l"(d) : "l"(a), "l"(b));
    return d;
}
__device__ __forceinline__ void unpk(unsigned long long v, float& lo, float& hi) {
    asm("mov.b64 {%0,%1}, %2;" : "=f"(lo), "=f"(hi) : "l"(v));
}
__device__ __forceinline__ void lds2(unsigned long long& a, unsigned long long& b,
                                     uint32_t addr) {
    asm volatile("ld.shared.v2.u64 {%0,%1}, [%2];" : "=l"(a), "=l"(b) : "r"(addr));
}
__device__ __forceinline__ void sts32(uint32_t addr, float v) {
    asm volatile("st.shared.f32 [%0], %1;" :: "r"(addr), "f"(v) : "memory");
}
__device__ __forceinline__ float lds32(uint32_t addr) {
    float v;
    asm volatile("ld.shared.f32 %0, [%1];" : "=f"(v) : "r"(addr));
    return v;
}

extern __shared__ float xs[];

__global__ void __launch_bounds__(TPB)
dtw_kernel(const float* __restrict__ x,
           const float* __restrict__ patts,
           float* __restrict__ out)
{
    const int tid  = threadIdx.x;
    const int warp = tid >> 5;
    const int lane = tid & 31;
    const int b    = blockIdx.x >> 3;
    const int ng   = blockIdx.x & 7;
    const float* xg = x + (size_t)b * DPD * LL;

    uint32_t xs_base;
    asm("{ .reg .u64 t; cvta.to.shared.u64 t, %1; cvt.u32.u64 %0, t; }"
        : "=r"(xs_base) : "l"(xs));

    // ---- x2 row into smem (x itself stays in global/L1) ----
    for (int j = tid; j < LL; j += TPB) {
        float s = 0.f;
        #pragma unroll
        for (int d = 0; d < DPD; ++d) {
            float v = __ldg(xg + d * LL + j);
            s = fmaf(v, v, s);
        }
        xs[j] = s;
    }
    __syncthreads();

    const bool is_gen = (warp >= 2);

    // ---- gen state: warps 2-9; gw = warp-2; problem w = gw>>1, half h = gw&1 ----
    unsigned long long qpd[DPD];
    unsigned long long p2p = 0;
    uint32_t gring = 0;
    int gh = 0;
    if (is_gen) {
        const int gw = warp - 2;
        const int w  = gw >> 1;
        gh = gw & 1;
        const int n = ng * 4 + w;
        gring = xs_base + (uint32_t)(XW + w * RINGW) * 4u;
        float p2 = 0.f;
        #pragma unroll
        for (int d = 0; d < DPD; ++d) {
            float pv = patts[(n * DPD + d) * 32 + lane];   // gen lane = pattern row
            p2 = fmaf(pv, pv, p2);
            float m = -2.f * pv;
            qpd[d] = pk2(m, m);
        }
        p2p = pk2(p2, p2);
    }

    // produce 16 cost columns c0..c0+15 (c0 multiple of 16) into ring[slot][row=lane]
    auto gen16 = [&](int c0) {
        const int s0 = c0 & (SLOTS - 1);
        unsigned long long acc[8];
        {   // x2 + p2
            uint32_t a2 = xs_base + (uint32_t)c0 * 4u;
            unsigned long long v0, v1, v2, v3, v4, v5, v6, v7;
            lds2(v0, v1, a2);       lds2(v2, v3, a2 + 16);
            lds2(v4, v5, a2 + 32);  lds2(v6, v7, a2 + 48);
            acc[0] = add2(v0, p2p); acc[1] = add2(v1, p2p);
            acc[2] = add2(v2, p2p); acc[3] = add2(v3, p2p);
            acc[4] = add2(v4, p2p); acc[5] = add2(v5, p2p);
            acc[6] = add2(v6, p2p); acc[7] = add2(v7, p2p);
        }
        #pragma unroll
        for (int d = 0; d < DPD; ++d) {
            const ulonglong2* pd = (const ulonglong2*)(xg + d * LL + c0);
            ulonglong2 q0 = __ldg(pd);
            ulonglong2 q1 = __ldg(pd + 1);
            ulonglong2 q2 = __ldg(pd + 2);
            ulonglong2 q3 = __ldg(pd + 3);
            acc[0] = fma2(qpd[d], q0.x, acc[0]);
            acc[1] = fma2(qpd[d], q0.y, acc[1]);
            acc[2] = fma2(qpd[d], q1.x, acc[2]);
            acc[3] = fma2(qpd[d], q1.y, acc[3]);
            acc[4] = fma2(qpd[d], q2.x, acc[4]);
            acc[5] = fma2(qpd[d], q2.y, acc[5]);
            acc[6] = fma2(qpd[d], q3.x, acc[6]);
            acc[7] = fma2(qpd[d], q3.y, acc[7]);
        }
        uint32_t sb = gring + (uint32_t)(SLOTM * s0 + lane) * 4u;
        #pragma unroll
        for (int k = 0; k < 8; ++k) {
            float lo, hi; unpk(acc[k], lo, hi);
            sts32(sb + (uint32_t)(2 * k)     * (SLOTM * 4), lo);
            sts32(sb + (uint32_t)(2 * k + 1) * (SLOTM * 4), hi);
        }
    };

    // ---- DP state: warps 0-1, lane g of each half-warp owns rows 2g, 2g+1 ----
    const int g    = lane & 15;
    const int wdp  = warp * 2 + (lane >> 4);
    const int ndp  = ng * 4 + wdp;
    const uint32_t ringb = xs_base + (uint32_t)(XW + wdp * RINGW + 2 * g) * 4u;
    float a_prev  = BIGF;                  // D[2g,   jA-1]
    float a_prev2 = BIGF;                  // D[2g,   jA-2]
    float b_prev  = BIGF;                  // D[2g+1, jB-1]
    float u1_prev = (g == 0) ? 0.f : BIGF; // D[2g-1, jA-1]; seeds D[0,0]=c00
    float* outA = out + (((size_t)(b * NP + ndp)) * 32 + 2 * g) * LOUT;
    float* outB = outA + LOUT;

    // prefill cols 0..31
    if (is_gen) gen16(gh * 16);
    __syncthreads();

    for (int p = 0; p < NPH; ++p) {
        if (is_gen) {
            if (p <= 30) gen16(CH * (p + 1) + gh * 16);   // cols 32..1023
        } else {
            const int t0 = p * CH;
            const int u  = t0 - 2 * g;           // jA at s=0
            if (p == 0) {
                // head: j may be negative -> force BIG
                for (int s = 0; s < CH; ++s) {
                    float u1 = __shfl_up_sync(0xffffffffu, b_prev, 1, 16);
                    if (g == 0) u1 = BIGF;
                    float cA = lds32(ringb + 136u * ((unsigned)(u + s) & (SLOTS - 1)));
                    float cB = lds32(ringb + 136u * ((unsigned)(u + s - 1) & (SLOTS - 1)) + 4u);
                    float A = cA + fminf(fminf(u1, u1_prev), a_prev);
                    float B = cB + fminf(fminf(a_prev2, b_prev), a_prev);
                    if (u + s < 0)     A = BIGF;
                    if (u + s - 1 < 0) B = BIGF;
                    u1_prev = u1; a_prev2 = a_prev; a_prev = A; b_prev = B;
                }
            } else if (p < 31) {
                // main: all valid, no stores
                #pragma unroll
                for (int s = 0; s < CH; ++s) {
                    float u1 = __shfl_up_sync(0xffffffffu, b_prev, 1, 16);
                    if (g == 0) u1 = BIGF;
                    float cA = lds32(ringb + 136u * ((unsigned)(u + s) & (SLOTS - 1)));
                    float cB = lds32(ringb + 136u * ((unsigned)(u + s - 1) & (SLOTS - 1)) + 4u);
                    float A = cA + fminf(fminf(u1, u1_prev), a_prev);
                    float B = cB + fminf(fminf(a_prev2, b_prev), a_prev);
                    u1_prev = u1; a_prev2 = a_prev; a_prev = A; b_prev = B;
                }
            } else {
                // tail: stores for j in [992,1024); j>1023 cells garbage-fed but
                // provably never stored nor feeding valid cells
                for (int s = 0; s < CH; ++s) {
                    float u1 = __shfl_up_sync(0xffffffffu, b_prev, 1, 16);
                    if (g == 0) u1 = BIGF;
                    float cA = lds32(ringb + 136u * ((unsigned)(u + s) & (SLOTS - 1)));
                    float cB = lds32(ringb + 136u * ((unsigned)(u + s - 1) & (SLOTS - 1)) + 4u);
                    float A = cA + fminf(fminf(u1, u1_prev), a_prev);
                    float B = cB + fminf(fminf(a_prev2, b_prev), a_prev);
                    int jA = u + s;
                    unsigned joA = (unsigned)(jA - (LL - LOUT));
                    if (joA < (unsigned)LOUT) outA[joA] = A;
                    unsigned joB = (unsigned)(jA - 1 - (LL - LOUT));
                    if (joB < (unsigned)LOUT) outB[joB] = B;
                    u1_prev = u1; a_prev2 = a_prev; a_prev = A; b_prev = B;
                }
            }
        }
        __syncthreads();
    }
}

extern "C" void kernel_launch(void* const* d_in, const int* in_sizes, int n_in,
                              void* d_out, int out_size)
{
    const float* x     = (const float*)d_in[0];   // [32, 12, 1024]
    const float* patts = (const float*)d_in[1];   // [32, 12, 32]
    float* out         = (float*)d_out;           // [32, 32, 32, 32]

    const int smem = SMEMW * sizeof(float);       // 73744 B
    cudaFuncSetAttribute(dtw_kernel, cudaFuncAttributeMaxDynamicSharedMemorySize, smem);
    dtw_kernel<<<B_ * (NP / 4), TPB, smem>>>(x, patts, out);
}